// round 1
// baseline (speedup 1.0000x reference)
#include <cuda_runtime.h>

#define BB   4
#define NN   512
#define FD   256
#define AD   256
#define DP   64
#define PD   128
#define ROWS (BB*NN)          /* 2048 */
#define NPAIR (BB*NN*NN)      /* 1048576 */
#define EPSF 1e-3f
#define SCAL 0.0625f          /* 1/sqrt(256) */

#define QK_TILES   256        /* 32 (M/64) * 8 (512/64) */
#define BIAS_BLOCKS 8192      /* 1048576 rows / 128 rows per block */

// ---------------- scratch (device globals; no allocation allowed) ----------
__device__ float d_Fn[ROWS*FD];
__device__ float d_Q[ROWS*AD];
__device__ float d_K[ROWS*AD];
__device__ float d_vsum[ROWS];
__device__ float d_gw[DP];
__device__ float d_sgw;
__device__ float d_bconst;
__device__ float d_wvsum[FD];
__device__ float d_bias[NPAIR];
__device__ float d_S[NPAIR];

// ---------------- helpers ---------------------------------------------------
__device__ __forceinline__ float block_sum256(float v, float* red) {
    int t = threadIdx.x;
    red[t] = v; __syncthreads();
    #pragma unroll
    for (int o = 128; o > 0; o >>= 1) {
        if (t < o) red[t] += red[t + o];
        __syncthreads();
    }
    float r = red[0]; __syncthreads();
    return r;
}

__device__ __forceinline__ float block_max256(float v, float* red) {
    int t = threadIdx.x;
    red[t] = v; __syncthreads();
    #pragma unroll
    for (int o = 128; o > 0; o >>= 1) {
        if (t < o) red[t] = fmaxf(red[t], red[t + o]);
        __syncthreads();
    }
    float r = red[0]; __syncthreads();
    return r;
}

// ---------------- K1: prep (w_eff, gw, sgw, bconst, wv_sum) -----------------
__global__ void prep_kernel(const float* __restrict__ Wv,
                            const float* __restrict__ gp,
                            const float* __restrict__ bp,
                            const float* __restrict__ Wpt,
                            const float* __restrict__ bpt,
                            const float* __restrict__ Wph) {
    __shared__ float red[256];
    int t = threadIdx.x;

    // wv_sum[f] = sum_a Wv[f,a]
    float s = 0.f;
    #pragma unroll 4
    for (int a = 0; a < AD; a++) s += Wv[t*AD + a];
    d_wvsum[t] = s;

    // w_eff[c] = sum_p Wpt[c,p]*Wph[p];  gw[c] = g_p[c]*w_eff[c]
    float we = 0.f;
    if (t < DP) {
        #pragma unroll 4
        for (int p = 0; p < PD; p++) we += Wpt[t*PD + p] * Wph[p];
        d_gw[t] = gp[t] * we;
    }
    float v_sgw = (t < DP) ? gp[t] * we : 0.f;
    float v_bc  = (t < DP) ? bp[t] * we : 0.f;
    float v_bpt = (t < PD) ? bpt[t] * Wph[t] : 0.f;

    float sgw = block_sum256(v_sgw, red);
    float bc  = block_sum256(v_bc + v_bpt, red);
    if (t == 0) { d_sgw = sgw; d_bconst = bc; }
}

// ---------------- K2: LayerNorm(F) -> Fn, vsum ------------------------------
__global__ void lnf_kernel(const float* __restrict__ F,
                           const float* __restrict__ gf,
                           const float* __restrict__ bf) {
    __shared__ float red[256];
    int r = blockIdx.x;
    int t = threadIdx.x;
    float x  = F[r*FD + t];
    float mu = block_sum256(x, red) * (1.f/FD);
    float sq = block_sum256(x*x, red) * (1.f/FD);
    float rstd = rsqrtf(sq - mu*mu + EPSF);
    float fn = (x - mu) * rstd * gf[t] + bf[t];
    d_Fn[r*FD + t] = fn;
    float vs = block_sum256(fn * d_wvsum[t], red);
    if (t == 0) d_vsum[r] = vs;
}

// ---------------- K3: fused  [Q,K]=Fn@[Wq|Wk]  ||  bias from D --------------
// blocks [0, QK_TILES)          : fp32 tiled GEMM (compute-bound)
// blocks [QK_TILES, +BIAS_BLOCKS): D sweep (HBM-bound) -- overlap in one launch
__global__ void __launch_bounds__(256)
qk_bias_kernel(const float* __restrict__ Dm,
               const float* __restrict__ Wq,
               const float* __restrict__ Wk) {
    __shared__ float As[16][65];
    __shared__ float Bs[16][65];
    __shared__ float gwsh[DP];
    int tid = threadIdx.x;

    if (blockIdx.x < QK_TILES) {
        // ---- GEMM: C[2048 x 512] = Fn[2048 x 256] @ [Wq | Wk] ----
        int bm = blockIdx.x & 31;          // M tile
        int bn = blockIdx.x >> 5;          // N tile (0..7)
        int row0 = bm * 64;
        int n0   = bn * 64;
        const float* Bmat = (n0 < AD) ? Wq : Wk;
        int ncol0 = (n0 < AD) ? n0 : (n0 - AD);
        float* Cout = (n0 < AD) ? d_Q : d_K;

        int lm = tid >> 2;                 // 0..63 (A row within tile)
        int lk = (tid & 3) * 4;            // 0,4,8,12 (k offset)
        int bk = tid >> 4;                 // 0..15 (B k-row)
        int bn4 = (tid & 15) * 4;          // B col offset
        int ty = tid >> 4, tx = tid & 15;

        float acc[4][4] = {};
        for (int kt = 0; kt < FD; kt += 16) {
            float4 a = *(const float4*)&d_Fn[(row0 + lm)*FD + kt + lk];
            As[lk+0][lm] = a.x; As[lk+1][lm] = a.y;
            As[lk+2][lm] = a.z; As[lk+3][lm] = a.w;
            float4 b = *(const float4*)&Bmat[(kt + bk)*AD + ncol0 + bn4];
            Bs[bk][bn4+0] = b.x; Bs[bk][bn4+1] = b.y;
            Bs[bk][bn4+2] = b.z; Bs[bk][bn4+3] = b.w;
            __syncthreads();
            #pragma unroll
            for (int kf = 0; kf < 16; kf++) {
                float av[4], bv[4];
                #pragma unroll
                for (int i = 0; i < 4; i++) av[i] = As[kf][ty*4 + i];
                #pragma unroll
                for (int j = 0; j < 4; j++) bv[j] = Bs[kf][tx*4 + j];
                #pragma unroll
                for (int i = 0; i < 4; i++)
                    #pragma unroll
                    for (int j = 0; j < 4; j++)
                        acc[i][j] += av[i] * bv[j];
            }
            __syncthreads();
        }
        #pragma unroll
        for (int i = 0; i < 4; i++) {
            int r = row0 + ty*4 + i;
            #pragma unroll
            for (int j = 0; j < 4; j++)
                Cout[r*AD + ncol0 + tx*4 + j] = acc[i][j];
        }
    } else {
        // ---- bias: per pair-row LN(64) folded with w_eff ----
        if (tid < DP) gwsh[tid] = d_gw[tid];
        __syncthreads();
        int bb = blockIdx.x - QK_TILES;
        int h = tid >> 4;                  // half-warp id 0..15
        int l = tid & 15;                  // lane in half-warp
        float gw0 = gwsh[l*4+0], gw1 = gwsh[l*4+1];
        float gw2 = gwsh[l*4+2], gw3 = gwsh[l*4+3];
        float sgw = d_sgw, bconst = d_bconst;
        int base = bb * 128;
        #pragma unroll
        for (int it = 0; it < 8; it++) {
            int row = base + it*16 + h;
            float4 v = *(const float4*)&Dm[(size_t)row*DP + l*4];
            float s1 = v.x + v.y + v.z + v.w;
            float s2 = v.x*v.x + v.y*v.y + v.z*v.z + v.w*v.w;
            float s3 = v.x*gw0 + v.y*gw1 + v.z*gw2 + v.w*gw3;
            #pragma unroll
            for (int o = 8; o > 0; o >>= 1) {
                s1 += __shfl_down_sync(0xffffffffu, s1, o, 16);
                s2 += __shfl_down_sync(0xffffffffu, s2, o, 16);
                s3 += __shfl_down_sync(0xffffffffu, s3, o, 16);
            }
            if (l == 0) {
                float mu = s1 * (1.f/DP);
                float var = s2 * (1.f/DP) - mu*mu;
                float rstd = rsqrtf(var + EPSF);
                d_bias[row] = rstd * (s3 - mu*sgw) + bconst;
            }
        }
    }
}

// ---------------- K4: S = SCAL * (Q @ K^T + bias)  (batched NT GEMM) --------
__global__ void __launch_bounds__(256)
s_gemm_kernel() {
    __shared__ float As[16][65];
    __shared__ float Bs[16][65];
    int b  = blockIdx.z;
    int q0 = blockIdx.y * 64;
    int k0 = blockIdx.x * 64;
    const float* A  = d_Q + b*NN*AD;
    const float* Bm = d_K + b*NN*AD;

    int tid = threadIdx.x;
    int lm = tid >> 2;
    int lk = (tid & 3) * 4;
    int ty = tid >> 4, tx = tid & 15;

    float acc[4][4] = {};
    for (int kt = 0; kt < AD; kt += 16) {
        float4 a = *(const float4*)&A[(q0 + lm)*AD + kt + lk];
        As[lk+0][lm] = a.x; As[lk+1][lm] = a.y;
        As[lk+2][lm] = a.z; As[lk+3][lm] = a.w;
        float4 c = *(const float4*)&Bm[(k0 + lm)*AD + kt + lk];
        Bs[lk+0][lm] = c.x; Bs[lk+1][lm] = c.y;
        Bs[lk+2][lm] = c.z; Bs[lk+3][lm] = c.w;
        __syncthreads();
        #pragma unroll
        for (int kf = 0; kf < 16; kf++) {
            float av[4], bv[4];
            #pragma unroll
            for (int i = 0; i < 4; i++) av[i] = As[kf][ty*4 + i];
            #pragma unroll
            for (int j = 0; j < 4; j++) bv[j] = Bs[kf][tx*4 + j];
            #pragma unroll
            for (int i = 0; i < 4; i++)
                #pragma unroll
                for (int j = 0; j < 4; j++)
                    acc[i][j] += av[i] * bv[j];
        }
        __syncthreads();
    }
    #pragma unroll
    for (int i = 0; i < 4; i++) {
        int q = q0 + ty*4 + i;
        int idx = (b*NN + q)*NN + k0 + tx*4;
        #pragma unroll
        for (int j = 0; j < 4; j++)
            d_S[idx + j] = SCAL * (acc[i][j] + d_bias[idx + j]);
    }
}

// ---------------- K5: softmax over k + dot with vsum ------------------------
__global__ void softmax_out_kernel(float* __restrict__ out) {
    __shared__ float red[256];
    int r = blockIdx.x;          // 0..2047 = b*512 + q
    int b = r >> 9;
    int t = threadIdx.x;
    float s0 = d_S[r*NN + t];
    float s1 = d_S[r*NN + 256 + t];
    float m = block_max256(fmaxf(s0, s1), red);
    float e0 = expf(s0 - m), e1 = expf(s1 - m);
    float v0 = d_vsum[b*NN + t], v1 = d_vsum[b*NN + 256 + t];
    float se = block_sum256(e0 + e1, red);
    float sv = block_sum256(e0*v0 + e1*v1, red);
    if (t == 0) out[r] = sv / se;
}

// ---------------- launch ----------------------------------------------------
extern "C" void kernel_launch(void* const* d_in, const int* in_sizes, int n_in,
                              void* d_out, int out_size) {
    const float* F   = (const float*)d_in[0];
    const float* Dm  = (const float*)d_in[1];
    const float* Wq  = (const float*)d_in[2];
    const float* Wk  = (const float*)d_in[3];
    const float* Wv  = (const float*)d_in[4];
    const float* gf  = (const float*)d_in[5];
    const float* bf  = (const float*)d_in[6];
    const float* gp  = (const float*)d_in[7];
    const float* bp  = (const float*)d_in[8];
    const float* Wpt = (const float*)d_in[9];
    const float* bpt = (const float*)d_in[10];
    const float* Wph = (const float*)d_in[11];
    float* out = (float*)d_out;

    prep_kernel<<<1, 256>>>(Wv, gp, bp, Wpt, bpt, Wph);
    lnf_kernel<<<ROWS, 256>>>(F, gf, bf);
    qk_bias_kernel<<<QK_TILES + BIAS_BLOCKS, 256>>>(Dm, Wq, Wk);
    dim3 g4(NN/64, NN/64, BB);
    s_gemm_kernel<<<g4, 256>>>();
    softmax_out_kernel<<<ROWS, 256>>>(out);
}